// round 1
// baseline (speedup 1.0000x reference)
#include <cuda_runtime.h>
#include <math.h>

#define BN_EPS 1e-5f
#define SPB 32
#define NTHREADS 256
#define MAXB 65536

// persistent scratch (no allocation allowed)
__device__ float g_Ure[256];
__device__ float g_Uim[256];
__device__ float g_zbuf[MAXB * 4];
__device__ float g_part[(MAXB / SPB) * 8];
__device__ float g_stats[8];

// ---------------------------------------------------------------------------
// Kernel 0: build the fixed 16x16 variational unitary U (columns = evolved
// basis states). 16 threads, each evolves one basis vector, fully unrolled.
// Wire i <-> bit mask (8 >> i)  (wire 0 = MSB, matching axis order of the ref)
// ---------------------------------------------------------------------------
__global__ void k_build_u(const float* __restrict__ vp) {
    int t = threadIdx.x;
    if (t >= 16) return;
    float re[16], im[16];
#pragma unroll
    for (int b = 0; b < 16; b++) { re[b] = (b == t) ? 1.f : 0.f; im[b] = 0.f; }
#pragma unroll
    for (int d = 0; d < 2; d++) {
#pragma unroll
        for (int w = 0; w < 4; w++) {
            const int mask = 8 >> w;
            float cx, sx, cy, sy, cz, sz;
            sincosf(0.5f * vp[d * 12 + w * 3 + 0], &sx, &cx);
            sincosf(0.5f * vp[d * 12 + w * 3 + 1], &sy, &cy);
            sincosf(0.5f * vp[d * 12 + w * 3 + 2], &sz, &cz);
#pragma unroll
            for (int b = 0; b < 16; b++) {
                if (b & mask) continue;
                const int b1 = b | mask;
                float r0, i0, r1, i1;
                // RX: [[c,-is],[-is,c]]
                r0 = re[b]; i0 = im[b]; r1 = re[b1]; i1 = im[b1];
                re[b]  = cx * r0 + sx * i1;  im[b]  = cx * i0 - sx * r1;
                re[b1] = cx * r1 + sx * i0;  im[b1] = cx * i1 - sx * r0;
                // RY: [[c,-s],[s,c]]
                r0 = re[b]; i0 = im[b]; r1 = re[b1]; i1 = im[b1];
                re[b]  = cy * r0 - sy * r1;  im[b]  = cy * i0 - sy * i1;
                re[b1] = sy * r0 + cy * r1;  im[b1] = sy * i0 + cy * i1;
                // RZ: diag(e^{-i t/2}, e^{+i t/2})
                r0 = re[b]; i0 = im[b]; r1 = re[b1]; i1 = im[b1];
                re[b]  = cz * r0 + sz * i0;  im[b]  = cz * i0 - sz * r0;
                re[b1] = cz * r1 - sz * i1;  im[b1] = cz * i1 + sz * r1;
            }
        }
        // CNOT ring (0,1),(1,2),(2,3),(3,0): swap amplitudes with ctrl=1
#pragma unroll
        for (int c = 0; c < 4; c++) {
            const int tg = (c + 1) & 3;
            const int mc = 8 >> c, mt = 8 >> tg;
#pragma unroll
            for (int b = 0; b < 16; b++) {
                if ((b & mc) && !(b & mt)) {
                    const int b1 = b | mt;
                    float tr = re[b], ti = im[b];
                    re[b] = re[b1]; im[b] = im[b1];
                    re[b1] = tr;    im[b1] = ti;
                }
            }
        }
    }
#pragma unroll
    for (int b = 0; b < 16; b++) {
        g_Ure[b * 16 + t] = re[b];
        g_Uim[b * 16 + t] = im[b];
    }
}

// ---------------------------------------------------------------------------
// Kernel 1: main fused kernel. One block = 32 samples.
//  Phase A: coalesced float4 load of 32 rows (576 floats each) with
//           horizontal pool-partials computed at load time.
//  Phase B: vertical pooling -> pooled[32][16]
//  Phase C: circuit, 8 threads/sample (2 amplitudes each) + shfl reduce
//  Phase D: per-block sum / sumsq partials for BatchNorm
// ---------------------------------------------------------------------------
__global__ void __launch_bounds__(NTHREADS) k_main(
        const float* __restrict__ x,
        const float* __restrict__ enc_w,
        const float* __restrict__ enc_b,
        int B)
{
    // ph: per sample 24 rows * 6 quads * (A,B) floats, padded stride 290 floats
    __shared__ float ph[SPB * 290];        // 37120 B
    __shared__ float Us[2 * 16 * 17];      // padded U re|im
    __shared__ float pls[SPB * 17];        // pooled, padded
    __shared__ float encs[68];             // enc_w (64) + enc_b (4)
    __shared__ float zsm[SPB * 4];

    const int tid = threadIdx.x;

    // stage U (padded rows of 17 to kill LDS bank conflicts) and encoder
    {
        int b = tid >> 4, t = tid & 15;
        Us[b * 17 + t]       = g_Ure[tid];
        Us[272 + b * 17 + t] = g_Uim[tid];
    }
    if (tid < 64) encs[tid] = enc_w[tid];
    if (tid < 4)  encs[64 + tid] = enc_b[tid];

    // ---- Phase A: load + horizontal partial pooling ----
    const long base = (long)blockIdx.x * SPB * 576;
    const float4* x4 = (const float4*)(x + base);
    const int nsamp = min(SPB, B - blockIdx.x * SPB);
    const int nf4 = nsamp * 144;
#pragma unroll
    for (int k = 0; k < 18; k++) {
        int idx = tid + k * NTHREADS;
        if (idx < nf4) {
            float4 v = x4[idx];
            int s   = idx / 144;
            int r   = idx - s * 144;
            int row = r / 6;
            int q   = r - row * 6;
            float lo = v.x + v.y, hi = v.z + v.w;
            float A, Bv;
            if (q == 1 || q == 4) { A = lo; Bv = hi; }   // straddles 2 windows
            else                  { A = lo + hi; Bv = 0.f; }
            float* dst = ph + s * 290 + row * 12 + q * 2;
            dst[0] = A; dst[1] = Bv;
        }
    }
    __syncthreads();

    // ---- Phase B: vertical pooling (2 windows per thread) ----
#pragma unroll
    for (int k = 0; k < 2; k++) {
        int o = tid + k * NTHREADS;
        int s = o >> 4, w = o & 15;
        if (s < nsamp) {
            int wy = w >> 2, wx = w & 3;
            int o1 = wx * 3;                 // {0,3,6,9}
            int o2 = wx * 3 + 2 - (wx & 1);  // {2,4,8,10}
            const float* pb = ph + s * 290 + wy * 72;
            float sum = 0.f;
#pragma unroll
            for (int dy = 0; dy < 6; dy++)
                sum += pb[dy * 12 + o1] + pb[dy * 12 + o2];
            pls[s * 17 + w] = sum * (1.f / 36.f);
        }
    }
    __syncthreads();

    // ---- Phase C: circuit (8 threads per sample) ----
    const int s = tid >> 3;          // sample within block
    const int j = tid & 7;           // which pair of output amplitudes
    const int samp = blockIdx.x * SPB + s;
    float z0 = 0.f, z1 = 0.f, z2 = 0.f, z3 = 0.f;
    if (samp < B) {
        float pld[16];
#pragma unroll
        for (int kk = 0; kk < 16; kk++) pld[kk] = pls[s * 17 + kk];
        float ang[4];
#pragma unroll
        for (int i = 0; i < 4; i++) {
            float a = encs[64 + i];
#pragma unroll
            for (int kk = 0; kk < 16; kk++) a = fmaf(encs[i * 16 + kk], pld[kk], a);
            ang[i] = a;
        }
        float cc[4], ss[4];
#pragma unroll
        for (int i = 0; i < 4; i++) sincosf(0.5f * ang[i], &ss[i], &cc[i]);

        // psi_b = (-i)^popcount(b) * prod_i (bit ? s_i : c_i)
        float pr[16], pi[16];
#pragma unroll
        for (int b = 0; b < 16; b++) {
            float v = ((b & 8) ? ss[0] : cc[0]) * ((b & 4) ? ss[1] : cc[1])
                    * ((b & 2) ? ss[2] : cc[2]) * ((b & 1) ? ss[3] : cc[3]);
            const int k4 = __popc(b) & 3;
            pr[b] = (k4 == 0) ? v : ((k4 == 2) ? -v : 0.f);
            pi[b] = (k4 == 1) ? -v : ((k4 == 3) ? v : 0.f);
        }

        // two rows of U @ psi
        const int r0 = 2 * j, r1 = 2 * j + 1;
        const float* ur = Us;
        const float* ui = Us + 272;
        float ar0 = 0.f, ai0 = 0.f, ar1 = 0.f, ai1 = 0.f;
#pragma unroll
        for (int t = 0; t < 16; t++) {
            float u0r = ur[r0 * 17 + t], u0i = ui[r0 * 17 + t];
            float u1r = ur[r1 * 17 + t], u1i = ui[r1 * 17 + t];
            ar0 = fmaf(u0r, pr[t], fmaf(-u0i, pi[t], ar0));
            ai0 = fmaf(u0r, pi[t], fmaf( u0i, pr[t], ai0));
            ar1 = fmaf(u1r, pr[t], fmaf(-u1i, pi[t], ar1));
            ai1 = fmaf(u1r, pi[t], fmaf( u1i, pr[t], ai1));
        }
        float p0 = ar0 * ar0 + ai0 * ai0;
        float p1 = ar1 * ar1 + ai1 * ai1;
        z0 = ((r0 & 8) ? -p0 : p0) + ((r1 & 8) ? -p1 : p1);
        z1 = ((r0 & 4) ? -p0 : p0) + ((r1 & 4) ? -p1 : p1);
        z2 = ((r0 & 2) ? -p0 : p0) + ((r1 & 2) ? -p1 : p1);
        z3 = p0 - p1;   // r0 has bit0=0, r1 has bit0=1
    }
    // reduce across the 8 lanes of each sample group
#pragma unroll
    for (int off = 4; off >= 1; off >>= 1) {
        z0 += __shfl_down_sync(0xffffffffu, z0, off);
        z1 += __shfl_down_sync(0xffffffffu, z1, off);
        z2 += __shfl_down_sync(0xffffffffu, z2, off);
        z3 += __shfl_down_sync(0xffffffffu, z3, off);
    }
    if (j == 0) {
        zsm[s * 4 + 0] = z0; zsm[s * 4 + 1] = z1;
        zsm[s * 4 + 2] = z2; zsm[s * 4 + 3] = z3;
        if (samp < B) {
            ((float4*)g_zbuf)[samp] = make_float4(z0, z1, z2, z3);
        }
    }
    __syncthreads();

    // ---- Phase D: block partials for BatchNorm (deterministic) ----
    if (tid < 4) {
        float S = 0.f, SS = 0.f;
#pragma unroll
        for (int g = 0; g < SPB; g++) {
            float v = zsm[g * 4 + tid];
            S += v; SS += v * v;
        }
        g_part[blockIdx.x * 8 + tid]     = S;
        g_part[blockIdx.x * 8 + 4 + tid] = SS;
    }
}

// ---------------------------------------------------------------------------
// Kernel 2: reduce partials -> mean/var -> scale/shift
// ---------------------------------------------------------------------------
__global__ void k_stats(const float* __restrict__ gamma,
                        const float* __restrict__ beta,
                        int nb, int B)
{
    __shared__ float red[256];
    const int tid = threadIdx.x;
    const int w = tid & 7, r = tid >> 3;
    float S = 0.f;
    for (int i = r; i < nb; i += 32) S += g_part[i * 8 + w];
    red[tid] = S;
    __syncthreads();
#pragma unroll
    for (int step = 128; step >= 8; step >>= 1) {
        if (tid < step) red[tid] += red[tid + step];
        __syncthreads();
    }
    if (tid < 4) {
        float mean = red[tid] / (float)B;
        float var  = red[4 + tid] / (float)B - mean * mean;
        float scale = gamma[tid] * rsqrtf(var + BN_EPS);
        g_stats[tid]     = scale;
        g_stats[4 + tid] = beta[tid] - mean * scale;
    }
}

// ---------------------------------------------------------------------------
// Kernel 3: normalize z -> out
// ---------------------------------------------------------------------------
__global__ void k_norm(float* __restrict__ out, int B) {
    const float s0 = g_stats[0], s1 = g_stats[1], s2 = g_stats[2], s3 = g_stats[3];
    const float h0 = g_stats[4], h1 = g_stats[5], h2 = g_stats[6], h3 = g_stats[7];
    const int stride = gridDim.x * blockDim.x;
    const float4* zin = (const float4*)g_zbuf;
    float4* o4 = (float4*)out;
    for (int b = blockIdx.x * blockDim.x + threadIdx.x; b < B; b += stride) {
        float4 z = zin[b];
        o4[b] = make_float4(fmaf(z.x, s0, h0), fmaf(z.y, s1, h1),
                            fmaf(z.z, s2, h2), fmaf(z.w, s3, h3));
    }
}

extern "C" void kernel_launch(void* const* d_in, const int* in_sizes, int n_in,
                              void* d_out, int out_size)
{
    const float* x      = (const float*)d_in[0];
    const float* enc_w  = (const float*)d_in[1];
    const float* enc_b  = (const float*)d_in[2];
    const float* vp     = (const float*)d_in[3];
    const float* gamma  = (const float*)d_in[4];
    const float* beta   = (const float*)d_in[5];

    const int B  = in_sizes[0] / 576;      // [B,1,24,24]
    const int nb = (B + SPB - 1) / SPB;

    k_build_u<<<1, 32>>>(vp);
    k_main<<<nb, NTHREADS>>>(x, enc_w, enc_b, B);
    k_stats<<<1, 256>>>(gamma, beta, nb, B);
    int gb = (B + 255) / 256; if (gb > 256) gb = 256;
    k_norm<<<gb, 256>>>((float*)d_out, B);
}